// round 5
// baseline (speedup 1.0000x reference)
#include <cuda_runtime.h>
#include <cuda_bf16.h>
#include <math_constants.h>
#include <cstdint>

#define T_TOK 32768
#define H_DIM 1024
#define V_DIM 32
#define D_DIM 1024
#define KEXP  2048          // [hi | lo] storage width

// ---- scratch (static device globals; zero-initialized at module load) ----
__device__ int   g_tok[T_TOK];
__device__ int   g_run_start[T_TOK];
__device__ int   g_run_dest[T_TOK];
__device__ int   g_R;
__device__ int   g_nvalid;
__device__ __nv_bfloat16 g_A[(size_t)T_TOK * KEXP];   // rows >= n_valid stay 0
__device__ __nv_bfloat16 g_W[(size_t)D_DIM * KEXP];

// ============================================================
// helpers
// ============================================================
__device__ __forceinline__ uint32_t smem_u32(const void* p) {
    return (uint32_t)__cvta_generic_to_shared(p);
}
__device__ __forceinline__ void cp16(uint32_t dst, const void* src) {
    asm volatile("cp.async.cg.shared.global [%0], [%1], 16;\n" :: "r"(dst), "l"(src));
}
__device__ __forceinline__ void ldmx4(uint32_t* r, uint32_t a) {
    asm volatile("ldmatrix.sync.aligned.m8n8.x4.shared.b16 {%0,%1,%2,%3}, [%4];"
                 : "=r"(r[0]), "=r"(r[1]), "=r"(r[2]), "=r"(r[3]) : "r"(a));
}
__device__ __forceinline__ void mma16816(float* c, const uint32_t* a, const uint32_t* b) {
    asm volatile(
        "mma.sync.aligned.m16n8k16.row.col.f32.bf16.bf16.f32 "
        "{%0,%1,%2,%3},{%4,%5,%6,%7},{%8,%9},{%0,%1,%2,%3};"
        : "+f"(c[0]), "+f"(c[1]), "+f"(c[2]), "+f"(c[3])
        : "r"(a[0]), "r"(a[1]), "r"(a[2]), "r"(a[3]), "r"(b[0]), "r"(b[1]));
}
#define SW128(o) ((o) ^ (((o) >> 3) & 0x70))

// ============================================================
// K1: argmax over V=32 (first-occurrence tie-break)
// ============================================================
__global__ void k_argmax(const float* __restrict__ logits) {
    int t = blockIdx.x * blockDim.x + threadIdx.x;
    if (t >= T_TOK) return;
    const float4* p = (const float4*)(logits + (size_t)t * V_DIM);
    float best = -CUDART_INF_F;
    int bi = 0;
#pragma unroll
    for (int i = 0; i < 8; i++) {
        float4 v = p[i];
        float vals[4] = {v.x, v.y, v.z, v.w};
#pragma unroll
        for (int j = 0; j < 4; j++)
            if (vals[j] > best) { best = vals[j]; bi = i * 4 + j; }
    }
    g_tok[t] = bi;
}

// ============================================================
// K2: single-block run-length scan (1024 thr x 32 tokens)
// ============================================================
__global__ void k_scan() {
    __shared__ int sr[1024];
    __shared__ int sv[1024];
    int tid = threadIdx.x;
    int base = tid * 32;

    int rc = 0, vc = 0;
    int prev = (base == 0) ? -1 : g_tok[base - 1];
#pragma unroll
    for (int i = 0; i < 32; i++) {
        int tk = g_tok[base + i];
        if (tk != prev) { rc++; if (tk != 0) vc++; }
        prev = tk;
    }
    sr[tid] = rc; sv[tid] = vc;
    __syncthreads();
    for (int off = 1; off < 1024; off <<= 1) {
        int r = sr[tid], v = sv[tid];
        int ra = 0, va = 0;
        if (tid >= off) { ra = sr[tid - off]; va = sv[tid - off]; }
        __syncthreads();
        sr[tid] = r + ra; sv[tid] = v + va;
        __syncthreads();
    }
    int rbase = sr[tid] - rc;
    int vbase = sv[tid] - vc;
    if (tid == 1023) { g_R = sr[1023]; g_nvalid = sv[1023]; }

    prev = (base == 0) ? -1 : g_tok[base - 1];
#pragma unroll
    for (int i = 0; i < 32; i++) {
        int tk = g_tok[base + i];
        if (tk != prev) {
            g_run_start[rbase] = base + i;
            g_run_dest[rbase] = (tk != 0) ? vbase : -1;
            if (tk != 0) vbase++;
            rbase++;
        }
        prev = tk;
    }
}

// ============================================================
// K3: per-run mean -> split bf16 (hi | lo) rows of g_A
// ============================================================
__global__ void k_means(const float* __restrict__ hidden) {
    int r = blockIdx.x;
    if (r >= g_R) return;
    int d = g_run_dest[r];
    if (d < 0) return;
    int s = g_run_start[r];
    int e = (r + 1 < g_R) ? g_run_start[r + 1] : T_TOK;
    float inv = 1.0f / (float)(e - s);

    int c = threadIdx.x;  // 0..255, 4 floats each
    float4 acc = make_float4(0.f, 0.f, 0.f, 0.f);
    for (int row = s; row < e; row++) {
        float4 v = ((const float4*)(hidden + (size_t)row * H_DIM))[c];
        acc.x += v.x; acc.y += v.y; acc.z += v.z; acc.w += v.w;
    }
    float m[4] = {acc.x * inv, acc.y * inv, acc.z * inv, acc.w * inv};
    __nv_bfloat16 hi[4], lo[4];
#pragma unroll
    for (int j = 0; j < 4; j++) {
        hi[j] = __float2bfloat16(m[j]);
        lo[j] = __float2bfloat16(m[j] - __bfloat162float(hi[j]));
    }
    size_t base = (size_t)d * KEXP + c * 4;
    *(uint2*)(g_A + base)        = *(uint2*)hi;
    *(uint2*)(g_A + base + 1024) = *(uint2*)lo;
}

// ============================================================
// K4: split W (fp32 -> bf16 hi | lo)
// ============================================================
__global__ void k_wsplit(const float* __restrict__ W) {
    int i = blockIdx.x * 256 + threadIdx.x;   // 0 .. 1M-1
    float v = W[i];
    __nv_bfloat16 hi = __float2bfloat16(v);
    __nv_bfloat16 lo = __float2bfloat16(v - __bfloat162float(hi));
    int r = i >> 10, c = i & 1023;
    g_W[(size_t)r * KEXP + c]        = hi;
    g_W[(size_t)r * KEXP + 1024 + c] = lo;
}

// ============================================================
// K5: mma.sync bf16 GEMM, 128x128 CTA tile.
// q-grouped stages: one 64KB stage = {A_hi, A_lo, W_hi, W_lo} for 64 k-cols;
// 3 split passes (hh, lh, hl) run from the same stage. 16 q-steps, 3 stages.
// ============================================================
#define BM 128
#define BN 128
#define KQ 16
#define OFF_ALO 16384
#define OFF_WHI 32768
#define OFF_WLO 49152
#define STAGE_BYTES 65536
#define SMEM_REQ (3 * STAGE_BYTES)

__device__ __forceinline__ void load_stage(uint32_t sb, int q, int row0, int col0, int tid) {
    uint32_t st = sb + (q % 3) * STAGE_BYTES;
    const __nv_bfloat16* Ab = g_A + (size_t)row0 * KEXP + q * 64;
    const __nv_bfloat16* Wb = g_W + (size_t)col0 * KEXP + q * 64;
#pragma unroll
    for (int i = 0; i < 4; i++) {        // 128 rows x 128B per part
        int c = i * 256 + tid;
        int r = c >> 3, k = c & 7;
        uint32_t off = SW128(r * 128 + k * 16);
        const size_t go = (size_t)r * KEXP + k * 8;
        cp16(st + off,           Ab + go);
        cp16(st + OFF_ALO + off, Ab + 1024 + go);
        cp16(st + OFF_WHI + off, Wb + go);
        cp16(st + OFF_WLO + off, Wb + 1024 + go);
    }
    asm volatile("cp.async.commit_group;\n" ::: "memory");
}

__global__ void __launch_bounds__(256, 1)
k_gemm_mma(const float* __restrict__ bias, float* __restrict__ out) {
    extern __shared__ char smem_raw[];
    uint32_t sb = smem_u32(smem_raw);
    const int tid = threadIdx.x;
    const int lane = tid & 31;
    const int wid = tid >> 5;
    const int row0 = blockIdx.y * BM;
    const int col0 = blockIdx.x * BN;
    const int wm = (wid & 1) * 64;     // warp M offset
    const int wn = (wid >> 1) * 32;    // warp N offset

    const int aRow = (lane & 7) + ((lane >> 3) & 1) * 8;
    const int aColB = (lane >> 4) * 16;
    const int bRow = (lane & 7) + (lane >> 4) * 8;
    const int bColB = ((lane >> 3) & 1) * 16;

    float acc[4][4][4];
#pragma unroll
    for (int i = 0; i < 4; i++)
#pragma unroll
        for (int j = 0; j < 4; j++)
#pragma unroll
            for (int k = 0; k < 4; k++) acc[i][j][k] = 0.f;

    load_stage(sb, 0, row0, col0, tid);
    load_stage(sb, 1, row0, col0, tid);

    for (int q = 0; q < KQ; q++) {
        if (q == KQ - 1) asm volatile("cp.async.wait_group 0;\n" ::: "memory");
        else             asm volatile("cp.async.wait_group 1;\n" ::: "memory");
        __syncthreads();

        if (q + 2 < KQ) load_stage(sb, q + 2, row0, col0, tid);

        uint32_t st = sb + (q % 3) * STAGE_BYTES;
#pragma unroll
        for (int kk = 0; kk < 4; kk++) {
            const uint32_t aoff = kk * 32 + aColB;
            const uint32_t boff = kk * 32 + bColB;
            uint32_t ah[4][4], al[4][4], wh[2][4], wl[2][4];
#pragma unroll
            for (int mt = 0; mt < 4; mt++)
                ldmx4(ah[mt], st + SW128((wm + mt * 16 + aRow) * 128 + aoff));
#pragma unroll
            for (int nt2 = 0; nt2 < 2; nt2++)
                ldmx4(wh[nt2], st + OFF_WHI + SW128((wn + nt2 * 16 + bRow) * 128 + boff));
            // pass 1: A_hi * W_hi
#pragma unroll
            for (int mt = 0; mt < 4; mt++)
#pragma unroll
                for (int nt = 0; nt < 4; nt++)
                    mma16816(acc[mt][nt], ah[mt], &wh[nt >> 1][(nt & 1) * 2]);
            // pass 2: A_lo * W_hi (reuse W_hi frags)
#pragma unroll
            for (int mt = 0; mt < 4; mt++)
                ldmx4(al[mt], st + OFF_ALO + SW128((wm + mt * 16 + aRow) * 128 + aoff));
#pragma unroll
            for (int mt = 0; mt < 4; mt++)
#pragma unroll
                for (int nt = 0; nt < 4; nt++)
                    mma16816(acc[mt][nt], al[mt], &wh[nt >> 1][(nt & 1) * 2]);
            // pass 3: A_hi * W_lo (reuse A_hi frags)
#pragma unroll
            for (int nt2 = 0; nt2 < 2; nt2++)
                ldmx4(wl[nt2], st + OFF_WLO + SW128((wn + nt2 * 16 + bRow) * 128 + boff));
#pragma unroll
            for (int mt = 0; mt < 4; mt++)
#pragma unroll
                for (int nt = 0; nt < 4; nt++)
                    mma16816(acc[mt][nt], ah[mt], &wl[nt >> 1][(nt & 1) * 2]);
        }
        __syncthreads();
    }

    // epilogue: +bias, mask rows >= n_valid, write fp32
    int nv = g_nvalid;
#pragma unroll
    for (int mt = 0; mt < 4; mt++) {
        int rbase = row0 + wm + mt * 16 + (lane >> 2);
#pragma unroll
        for (int h = 0; h < 2; h++) {
            int row = rbase + h * 8;
            bool valid = row < nv;
            float* orow = out + (size_t)row * D_DIM;
#pragma unroll
            for (int nt = 0; nt < 4; nt++) {
                int col = col0 + wn + nt * 8 + (lane & 3) * 2;
                float2 o;
                o.x = valid ? (acc[mt][nt][h * 2 + 0] + bias[col + 0]) : 0.f;
                o.y = valid ? (acc[mt][nt][h * 2 + 1] + bias[col + 1]) : 0.f;
                *(float2*)(orow + col) = o;
            }
        }
    }
}

// ============================================================
extern "C" void kernel_launch(void* const* d_in, const int* in_sizes, int n_in,
                              void* d_out, int out_size) {
    const float* hidden = (const float*)d_in[0];  // [1, T, H]
    const float* logits = (const float*)d_in[1];  // [1, T, V]
    const float* W      = (const float*)d_in[2];  // [D, H]
    const float* b      = (const float*)d_in[3];  // [D]
    float* out = (float*)d_out;                   // [1, T, D]

    cudaFuncSetAttribute(k_gemm_mma, cudaFuncAttributeMaxDynamicSharedMemorySize, SMEM_REQ);

    k_argmax<<<T_TOK / 256, 256>>>(logits);
    k_scan<<<1, 1024>>>();
    k_means<<<T_TOK, 256>>>(hidden);
    k_wsplit<<<(D_DIM * H_DIM) / 256, 256>>>(W);
    dim3 grid(D_DIM / BN, T_TOK / BM);
    k_gemm_mma<<<grid, 256, SMEM_REQ>>>(b, out);
}

// round 6
// speedup vs baseline: 1.3655x; 1.3655x over previous
#include <cuda_runtime.h>
#include <math_constants.h>
#include <cstdint>

#define T_TOK 32768
#define H_DIM 1024
#define V_DIM 32
#define D_DIM 1024

// ---- scratch (static device globals; zero-initialized at module load) ----
__device__ int    g_tok[T_TOK];
__device__ int    g_run_start[T_TOK];
__device__ int    g_run_dest[T_TOK];
__device__ int    g_R;
__device__ int    g_nvalid;
__device__ signed char g_Ah[(size_t)T_TOK * H_DIM];   // rows >= n_valid stay 0
__device__ signed char g_Al[(size_t)T_TOK * H_DIM];
__device__ signed char g_Wh[(size_t)D_DIM * H_DIM];
__device__ signed char g_Wl[(size_t)D_DIM * H_DIM];
__device__ float  g_sa[T_TOK];
__device__ float  g_sw[D_DIM];

// ============================================================
// helpers
// ============================================================
__device__ __forceinline__ uint32_t smem_u32(const void* p) {
    return (uint32_t)__cvta_generic_to_shared(p);
}
__device__ __forceinline__ void cp16(uint32_t dst, const void* src) {
    asm volatile("cp.async.cg.shared.global [%0], [%1], 16;\n" :: "r"(dst), "l"(src));
}
__device__ __forceinline__ void ldmx4(uint32_t* r, uint32_t a) {
    asm volatile("ldmatrix.sync.aligned.m8n8.x4.shared.b16 {%0,%1,%2,%3}, [%4];"
                 : "=r"(r[0]), "=r"(r[1]), "=r"(r[2]), "=r"(r[3]) : "r"(a));
}
__device__ __forceinline__ void imma16832(int* c, const uint32_t* a, const uint32_t* b) {
    asm volatile(
        "mma.sync.aligned.m16n8k32.row.col.s32.s8.s8.s32 "
        "{%0,%1,%2,%3},{%4,%5,%6,%7},{%8,%9},{%0,%1,%2,%3};"
        : "+r"(c[0]), "+r"(c[1]), "+r"(c[2]), "+r"(c[3])
        : "r"(a[0]), "r"(a[1]), "r"(a[2]), "r"(a[3]), "r"(b[0]), "r"(b[1]));
}
#define SW64(o) ((o) ^ (((o) >> 3) & 0x30))

// quantize one fp32 value into (h, l) int8 limbs given qs = 127/amax
__device__ __forceinline__ void quant2(float x, float qs, signed char& h8, signed char& l8) {
    float q = x * qs;                 // in [-127, 127]
    float h = rintf(q);
    float l = rintf((q - h) * 256.f);
    l = fminf(fmaxf(l, -128.f), 127.f);
    h8 = (signed char)(int)h;
    l8 = (signed char)(int)l;
}

// ============================================================
// K1: argmax over V=32 (first-occurrence tie-break)
// ============================================================
__global__ void k_argmax(const float* __restrict__ logits) {
    int t = blockIdx.x * blockDim.x + threadIdx.x;
    if (t >= T_TOK) return;
    const float4* p = (const float4*)(logits + (size_t)t * V_DIM);
    float best = -CUDART_INF_F;
    int bi = 0;
#pragma unroll
    for (int i = 0; i < 8; i++) {
        float4 v = p[i];
        float vals[4] = {v.x, v.y, v.z, v.w};
#pragma unroll
        for (int j = 0; j < 4; j++)
            if (vals[j] > best) { best = vals[j]; bi = i * 4 + j; }
    }
    g_tok[t] = bi;
}

// ============================================================
// K2: single-block run-length scan (1024 thr x 32 tokens)
// ============================================================
__global__ void k_scan() {
    __shared__ int sr[1024];
    __shared__ int sv[1024];
    int tid = threadIdx.x;
    int base = tid * 32;

    int rc = 0, vc = 0;
    int prev = (base == 0) ? -1 : g_tok[base - 1];
#pragma unroll
    for (int i = 0; i < 32; i++) {
        int tk = g_tok[base + i];
        if (tk != prev) { rc++; if (tk != 0) vc++; }
        prev = tk;
    }
    sr[tid] = rc; sv[tid] = vc;
    __syncthreads();
    for (int off = 1; off < 1024; off <<= 1) {
        int r = sr[tid], v = sv[tid];
        int ra = 0, va = 0;
        if (tid >= off) { ra = sr[tid - off]; va = sv[tid - off]; }
        __syncthreads();
        sr[tid] = r + ra; sv[tid] = v + va;
        __syncthreads();
    }
    int rbase = sr[tid] - rc;
    int vbase = sv[tid] - vc;
    if (tid == 1023) { g_R = sr[1023]; g_nvalid = sv[1023]; }

    prev = (base == 0) ? -1 : g_tok[base - 1];
#pragma unroll
    for (int i = 0; i < 32; i++) {
        int tk = g_tok[base + i];
        if (tk != prev) {
            g_run_start[rbase] = base + i;
            g_run_dest[rbase] = (tk != 0) ? vbase : -1;
            if (tk != 0) vbase++;
            rbase++;
        }
        prev = tk;
    }
}

// ============================================================
// K3: per-run mean -> quantize to int8 limbs (h, l) + scale
// ============================================================
__global__ void k_means(const float* __restrict__ hidden) {
    int r = blockIdx.x;
    if (r >= g_R) return;
    int d = g_run_dest[r];
    if (d < 0) return;
    int s = g_run_start[r];
    int e = (r + 1 < g_R) ? g_run_start[r + 1] : T_TOK;
    float inv = 1.0f / (float)(e - s);

    __shared__ float red[256];
    int c = threadIdx.x;  // 0..255, 4 floats each
    float4 acc = make_float4(0.f, 0.f, 0.f, 0.f);
    for (int row = s; row < e; row++) {
        float4 v = ((const float4*)(hidden + (size_t)row * H_DIM))[c];
        acc.x += v.x; acc.y += v.y; acc.z += v.z; acc.w += v.w;
    }
    float m[4] = {acc.x * inv, acc.y * inv, acc.z * inv, acc.w * inv};

    float am = fmaxf(fmaxf(fabsf(m[0]), fabsf(m[1])), fmaxf(fabsf(m[2]), fabsf(m[3])));
    red[c] = am;
    __syncthreads();
    for (int off = 128; off > 0; off >>= 1) {
        if (c < off) red[c] = fmaxf(red[c], red[c + off]);
        __syncthreads();
    }
    float amax = fmaxf(red[0], 1e-20f);
    float qs = 127.f / amax;
    if (c == 0) g_sa[d] = amax / 127.f;

    signed char h[4], l[4];
#pragma unroll
    for (int j = 0; j < 4; j++) quant2(m[j], qs, h[j], l[j]);
    size_t base = (size_t)d * H_DIM;
    ((char4*)(g_Ah + base))[c] = make_char4(h[0], h[1], h[2], h[3]);
    ((char4*)(g_Al + base))[c] = make_char4(l[0], l[1], l[2], l[3]);
}

// ============================================================
// K4: quantize W rows to int8 limbs (one block per row)
// ============================================================
__global__ void k_wquant(const float* __restrict__ W) {
    int r = blockIdx.x;          // 0..1023
    int c = threadIdx.x;         // 0..255, 4 floats each
    __shared__ float red[256];
    float4 v = ((const float4*)(W + (size_t)r * H_DIM))[c];
    float m[4] = {v.x, v.y, v.z, v.w};
    float am = fmaxf(fmaxf(fabsf(m[0]), fabsf(m[1])), fmaxf(fabsf(m[2]), fabsf(m[3])));
    red[c] = am;
    __syncthreads();
    for (int off = 128; off > 0; off >>= 1) {
        if (c < off) red[c] = fmaxf(red[c], red[c + off]);
        __syncthreads();
    }
    float amax = fmaxf(red[0], 1e-20f);
    float qs = 127.f / amax;
    if (c == 0) g_sw[r] = amax / 127.f;

    signed char h[4], l[4];
#pragma unroll
    for (int j = 0; j < 4; j++) quant2(m[j], qs, h[j], l[j]);
    size_t base = (size_t)r * H_DIM;
    ((char4*)(g_Wh + base))[c] = make_char4(h[0], h[1], h[2], h[3]);
    ((char4*)(g_Wl + base))[c] = make_char4(l[0], l[1], l[2], l[3]);
}

// ============================================================
// K5: int8 IMMA GEMM, 128x128 CTA tile, 512 threads, warp tile 32x32.
// Per k32: P1 += Ah*Wh (acc1); P23 += Al*Wh + Ah*Wl (acc2).
// BK=64 int8 (64B rows, SW64), stage = {Ah, Al, Wh, Wl} = 32KB, 3 stages.
// ============================================================
#define BM 128
#define BN 128
#define KQ 16
#define PART 8192
#define OFF_AL  PART
#define OFF_WH  (2 * PART)
#define OFF_WL  (3 * PART)
#define STAGE_BYTES (4 * PART)      // 32KB
#define SMEM_REQ (3 * STAGE_BYTES)  // 96KB

__device__ __forceinline__ void load_stage(uint32_t sb, int q, int row0, int col0, int tid) {
    uint32_t st = sb + (q % 3) * STAGE_BYTES;
    int r = tid >> 2;               // 0..127
    int ck = (tid & 3) * 16;        // 0,16,32,48
    uint32_t off = SW64(r * 64 + ck);
    size_t goA = (size_t)(row0 + r) * H_DIM + q * 64 + ck;
    size_t goW = (size_t)(col0 + r) * H_DIM + q * 64 + ck;
    cp16(st + off,           g_Ah + goA);
    cp16(st + OFF_AL + off,  g_Al + goA);
    cp16(st + OFF_WH + off,  g_Wh + goW);
    cp16(st + OFF_WL + off,  g_Wl + goW);
    asm volatile("cp.async.commit_group;\n" ::: "memory");
}

__global__ void __launch_bounds__(512, 1)
k_gemm_imma(const float* __restrict__ bias, float* __restrict__ out) {
    extern __shared__ char smem_raw[];
    uint32_t sb = smem_u32(smem_raw);
    const int tid = threadIdx.x;
    const int lane = tid & 31;
    const int wid = tid >> 5;        // 0..15
    const int row0 = blockIdx.y * BM;
    const int col0 = blockIdx.x * BN;
    const int wm = (wid & 3) * 32;   // warp M offset
    const int wn = (wid >> 2) * 32;  // warp N offset

    // ldmatrix per-lane address components (same mapping as validated bf16 version)
    const int aRow = (lane & 7) + ((lane >> 3) & 1) * 8;
    const int aColB = (lane >> 4) * 16;
    const int bRow = (lane & 7) + (lane >> 4) * 8;
    const int bColB = ((lane >> 3) & 1) * 16;

    int acc1[2][4][4];   // h*h
    int acc2[2][4][4];   // h*l + l*h
#pragma unroll
    for (int i = 0; i < 2; i++)
#pragma unroll
        for (int j = 0; j < 4; j++)
#pragma unroll
            for (int k = 0; k < 4; k++) { acc1[i][j][k] = 0; acc2[i][j][k] = 0; }

    load_stage(sb, 0, row0, col0, tid);
    load_stage(sb, 1, row0, col0, tid);

    for (int q = 0; q < KQ; q++) {
        if (q == KQ - 1) asm volatile("cp.async.wait_group 0;\n" ::: "memory");
        else             asm volatile("cp.async.wait_group 1;\n" ::: "memory");
        __syncthreads();

        if (q + 2 < KQ) load_stage(sb, q + 2, row0, col0, tid);

        uint32_t st = sb + (q % 3) * STAGE_BYTES;
#pragma unroll
        for (int kk = 0; kk < 2; kk++) {     // 2 x k32 per BK=64
            const uint32_t ao = kk * 32 + aColB;
            const uint32_t bo = kk * 32 + bColB;
            uint32_t ah[2][4], al[2][4], wh[2][4], wl[2][4];
#pragma unroll
            for (int mt = 0; mt < 2; mt++) {
                uint32_t ra = SW64((wm + mt * 16 + aRow) * 64 + ao);
                ldmx4(ah[mt], st + ra);
                ldmx4(al[mt], st + OFF_AL + ra);
            }
#pragma unroll
            for (int nb = 0; nb < 2; nb++) {
                uint32_t rb = SW64((wn + nb * 16 + bRow) * 64 + bo);
                ldmx4(wh[nb], st + OFF_WH + rb);
                ldmx4(wl[nb], st + OFF_WL + rb);
            }
#pragma unroll
            for (int mt = 0; mt < 2; mt++)
#pragma unroll
                for (int nt = 0; nt < 4; nt++) {
                    const uint32_t* bh = &wh[nt >> 1][(nt & 1) * 2];
                    const uint32_t* bl = &wl[nt >> 1][(nt & 1) * 2];
                    imma16832(acc1[mt][nt], ah[mt], bh);
                    imma16832(acc2[mt][nt], al[mt], bh);
                    imma16832(acc2[mt][nt], ah[mt], bl);
                }
        }
        __syncthreads();
    }

    // epilogue: out = valid ? sa*sw*(P1 + P23/256) + bias : 0
    int nv = g_nvalid;
#pragma unroll
    for (int mt = 0; mt < 2; mt++) {
        int rb = row0 + wm + mt * 16 + (lane >> 2);
#pragma unroll
        for (int h2 = 0; h2 < 2; h2++) {
            int row = rb + h2 * 8;
            bool valid = row < nv;
            float sa = g_sa[row];
            float* orow = out + (size_t)row * D_DIM;
#pragma unroll
            for (int nt = 0; nt < 4; nt++) {
                int col = col0 + wn + nt * 8 + (lane & 3) * 2;
                float p0 = (float)acc1[mt][nt][h2 * 2 + 0]
                         + (float)acc2[mt][nt][h2 * 2 + 0] * 0.00390625f;
                float p1 = (float)acc1[mt][nt][h2 * 2 + 1]
                         + (float)acc2[mt][nt][h2 * 2 + 1] * 0.00390625f;
                float2 o;
                o.x = valid ? (p0 * sa * g_sw[col + 0] + bias[col + 0]) : 0.f;
                o.y = valid ? (p1 * sa * g_sw[col + 1] + bias[col + 1]) : 0.f;
                *(float2*)(orow + col) = o;
            }
        }
    }
}

// ============================================================
extern "C" void kernel_launch(void* const* d_in, const int* in_sizes, int n_in,
                              void* d_out, int out_size) {
    const float* hidden = (const float*)d_in[0];  // [1, T, H]
    const float* logits = (const float*)d_in[1];  // [1, T, V]
    const float* W      = (const float*)d_in[2];  // [D, H]
    const float* b      = (const float*)d_in[3];  // [D]
    float* out = (float*)d_out;                   // [1, T, D]

    cudaFuncSetAttribute(k_gemm_imma, cudaFuncAttributeMaxDynamicSharedMemorySize, SMEM_REQ);

    k_argmax<<<T_TOK / 256, 256>>>(logits);
    k_scan<<<1, 1024>>>();
    k_means<<<T_TOK, 256>>>(hidden);
    k_wquant<<<D_DIM, 256>>>(W);
    dim3 grid(D_DIM / BN, T_TOK / BM);
    k_gemm_imma<<<grid, 512, SMEM_REQ>>>(b, out);
}

// round 8
// speedup vs baseline: 1.4325x; 1.0491x over previous
#include <cuda_runtime.h>
#include <math_constants.h>
#include <cstdint>

#define T_TOK 32768
#define H_DIM 1024
#define V_DIM 32
#define D_DIM 1024

// ---- scratch (static device globals; zero-initialized at module load) ----
__device__ int    g_tok[T_TOK];
__device__ int    g_run_start[T_TOK];
__device__ int    g_run_dest[T_TOK];
__device__ int    g_R;
__device__ int    g_nvalid;
__device__ signed char g_Ah[(size_t)T_TOK * H_DIM];   // rows >= n_valid stay 0
__device__ signed char g_Al[(size_t)T_TOK * H_DIM];
__device__ signed char g_Wh[(size_t)D_DIM * H_DIM];
__device__ signed char g_Wl[(size_t)D_DIM * H_DIM];
__device__ float  g_sa[T_TOK];
__device__ float  g_sw[D_DIM];

// ============================================================
// helpers
// ============================================================
__device__ __forceinline__ uint32_t smem_u32(const void* p) {
    return (uint32_t)__cvta_generic_to_shared(p);
}
__device__ __forceinline__ void cp16(uint32_t dst, const void* src) {
    asm volatile("cp.async.cg.shared.global [%0], [%1], 16;\n" :: "r"(dst), "l"(src));
}
__device__ __forceinline__ void ldmx4(uint32_t* r, uint32_t a) {
    asm volatile("ldmatrix.sync.aligned.m8n8.x4.shared.b16 {%0,%1,%2,%3}, [%4];"
                 : "=r"(r[0]), "=r"(r[1]), "=r"(r[2]), "=r"(r[3]) : "r"(a));
}
__device__ __forceinline__ void imma16832(int* c, const uint32_t* a, const uint32_t* b) {
    asm volatile(
        "mma.sync.aligned.m16n8k32.row.col.s32.s8.s8.s32 "
        "{%0,%1,%2,%3},{%4,%5,%6,%7},{%8,%9},{%0,%1,%2,%3};"
        : "+r"(c[0]), "+r"(c[1]), "+r"(c[2]), "+r"(c[3])
        : "r"(a[0]), "r"(a[1]), "r"(a[2]), "r"(a[3]), "r"(b[0]), "r"(b[1]));
}
#define SW64(o) ((o) ^ (((o) >> 3) & 0x30))

// quantize one fp32 value into (h, l) int8 limbs given qs = 127/amax
__device__ __forceinline__ void quant2(float x, float qs, signed char& h8, signed char& l8) {
    float q = x * qs;                 // in [-127, 127]
    float h = rintf(q);
    float l = rintf((q - h) * 256.f);
    l = fminf(fmaxf(l, -128.f), 127.f);
    h8 = (signed char)(int)h;
    l8 = (signed char)(int)l;
}

// ============================================================
// K1: argmax over V=32 (first-occurrence tie-break)
// ============================================================
__global__ void k_argmax(const float* __restrict__ logits) {
    int t = blockIdx.x * blockDim.x + threadIdx.x;
    if (t >= T_TOK) return;
    const float4* p = (const float4*)(logits + (size_t)t * V_DIM);
    float best = -CUDART_INF_F;
    int bi = 0;
#pragma unroll
    for (int i = 0; i < 8; i++) {
        float4 v = p[i];
        float vals[4] = {v.x, v.y, v.z, v.w};
#pragma unroll
        for (int j = 0; j < 4; j++)
            if (vals[j] > best) { best = vals[j]; bi = i * 4 + j; }
    }
    g_tok[t] = bi;
}

// ============================================================
// K2: single-block run-length scan (1024 thr x 32 tokens)
// ============================================================
__global__ void k_scan() {
    __shared__ int sr[1024];
    __shared__ int sv[1024];
    int tid = threadIdx.x;
    int base = tid * 32;

    int rc = 0, vc = 0;
    int prev = (base == 0) ? -1 : g_tok[base - 1];
#pragma unroll
    for (int i = 0; i < 32; i++) {
        int tk = g_tok[base + i];
        if (tk != prev) { rc++; if (tk != 0) vc++; }
        prev = tk;
    }
    sr[tid] = rc; sv[tid] = vc;
    __syncthreads();
    for (int off = 1; off < 1024; off <<= 1) {
        int r = sr[tid], v = sv[tid];
        int ra = 0, va = 0;
        if (tid >= off) { ra = sr[tid - off]; va = sv[tid - off]; }
        __syncthreads();
        sr[tid] = r + ra; sv[tid] = v + va;
        __syncthreads();
    }
    int rbase = sr[tid] - rc;
    int vbase = sv[tid] - vc;
    if (tid == 1023) { g_R = sr[1023]; g_nvalid = sv[1023]; }

    prev = (base == 0) ? -1 : g_tok[base - 1];
#pragma unroll
    for (int i = 0; i < 32; i++) {
        int tk = g_tok[base + i];
        if (tk != prev) {
            g_run_start[rbase] = base + i;
            g_run_dest[rbase] = (tk != 0) ? vbase : -1;
            if (tk != 0) vbase++;
            rbase++;
        }
        prev = tk;
    }
}

// ============================================================
// K3: per-run mean -> quantize to int8 limbs (h, l) + scale
// ============================================================
__global__ void k_means(const float* __restrict__ hidden) {
    int r = blockIdx.x;
    if (r >= g_R) return;
    int d = g_run_dest[r];
    if (d < 0) return;
    int s = g_run_start[r];
    int e = (r + 1 < g_R) ? g_run_start[r + 1] : T_TOK;
    float inv = 1.0f / (float)(e - s);

    __shared__ float red[256];
    int c = threadIdx.x;  // 0..255, 4 floats each
    float4 acc = make_float4(0.f, 0.f, 0.f, 0.f);
    for (int row = s; row < e; row++) {
        float4 v = ((const float4*)(hidden + (size_t)row * H_DIM))[c];
        acc.x += v.x; acc.y += v.y; acc.z += v.z; acc.w += v.w;
    }
    float m[4] = {acc.x * inv, acc.y * inv, acc.z * inv, acc.w * inv};

    float am = fmaxf(fmaxf(fabsf(m[0]), fabsf(m[1])), fmaxf(fabsf(m[2]), fabsf(m[3])));
    red[c] = am;
    __syncthreads();
    for (int off = 128; off > 0; off >>= 1) {
        if (c < off) red[c] = fmaxf(red[c], red[c + off]);
        __syncthreads();
    }
    float amax = fmaxf(red[0], 1e-20f);
    float qs = 127.f / amax;
    if (c == 0) g_sa[d] = amax / 127.f;

    signed char h[4], l[4];
#pragma unroll
    for (int j = 0; j < 4; j++) quant2(m[j], qs, h[j], l[j]);
    size_t base = (size_t)d * H_DIM;
    ((char4*)(g_Ah + base))[c] = make_char4(h[0], h[1], h[2], h[3]);
    ((char4*)(g_Al + base))[c] = make_char4(l[0], l[1], l[2], l[3]);
}

// ============================================================
// K4: quantize W rows to int8 limbs (one block per row)
// ============================================================
__global__ void k_wquant(const float* __restrict__ W) {
    int r = blockIdx.x;          // 0..1023
    int c = threadIdx.x;         // 0..255, 4 floats each
    __shared__ float red[256];
    float4 v = ((const float4*)(W + (size_t)r * H_DIM))[c];
    float m[4] = {v.x, v.y, v.z, v.w};
    float am = fmaxf(fmaxf(fabsf(m[0]), fabsf(m[1])), fmaxf(fabsf(m[2]), fabsf(m[3])));
    red[c] = am;
    __syncthreads();
    for (int off = 128; off > 0; off >>= 1) {
        if (c < off) red[c] = fmaxf(red[c], red[c + off]);
        __syncthreads();
    }
    float amax = fmaxf(red[0], 1e-20f);
    float qs = 127.f / amax;
    if (c == 0) g_sw[r] = amax / 127.f;

    signed char h[4], l[4];
#pragma unroll
    for (int j = 0; j < 4; j++) quant2(m[j], qs, h[j], l[j]);
    size_t base = (size_t)r * H_DIM;
    ((char4*)(g_Wh + base))[c] = make_char4(h[0], h[1], h[2], h[3]);
    ((char4*)(g_Wl + base))[c] = make_char4(l[0], l[1], l[2], l[3]);
}

// ============================================================
// K5: int8 IMMA GEMM, 128x128 CTA tile, 512 threads, warp tile 32x32.
// Per k32: P1 += Ah*Wh (acc1); P23 += Al*Wh + Ah*Wl (acc2).
// BK=64 int8 (64B rows, SW64), stage = {Ah, Al, Wh, Wl} = 32KB, 4 stages.
// Zero-skip fast path for tiles entirely past n_valid.
// ============================================================
#define BM 128
#define BN 128
#define KQ 16
#define PART 8192
#define OFF_AL  PART
#define OFF_WH  (2 * PART)
#define OFF_WL  (3 * PART)
#define STAGE_BYTES (4 * PART)      // 32KB
#define SMEM_REQ (4 * STAGE_BYTES)  // 128KB

__device__ __forceinline__ void load_stage(uint32_t sb, int q, int row0, int col0, int tid) {
    uint32_t st = sb + (q & 3) * STAGE_BYTES;
    int r = tid >> 2;               // 0..127
    int ck = (tid & 3) * 16;        // 0,16,32,48
    uint32_t off = SW64(r * 64 + ck);
    size_t goA = (size_t)(row0 + r) * H_DIM + q * 64 + ck;
    size_t goW = (size_t)(col0 + r) * H_DIM + q * 64 + ck;
    cp16(st + off,           g_Ah + goA);
    cp16(st + OFF_AL + off,  g_Al + goA);
    cp16(st + OFF_WH + off,  g_Wh + goW);
    cp16(st + OFF_WL + off,  g_Wl + goW);
    asm volatile("cp.async.commit_group;\n" ::: "memory");
}

__global__ void __launch_bounds__(512, 1)
k_gemm_imma(const float* __restrict__ bias, float* __restrict__ out) {
    extern __shared__ char smem_raw[];
    uint32_t sb = smem_u32(smem_raw);
    const int tid = threadIdx.x;
    const int lane = tid & 31;
    const int wid = tid >> 5;        // 0..15
    const int row0 = blockIdx.y * BM;
    const int col0 = blockIdx.x * BN;
    const int nv = g_nvalid;

    // fast path: tile entirely past the valid prefix -> zeros
    if (row0 >= nv) {
        float4 z = make_float4(0.f, 0.f, 0.f, 0.f);
#pragma unroll
        for (int i = 0; i < 8; i++) {
            int idx = i * 512 + tid;              // 4096 float4s
            int r = idx >> 5, c = (idx & 31) * 4;
            *(float4*)(out + (size_t)(row0 + r) * D_DIM + col0 + c) = z;
        }
        return;
    }

    const int wm = (wid & 3) * 32;   // warp M offset
    const int wn = (wid >> 2) * 32;  // warp N offset

    const int aRow = (lane & 7) + ((lane >> 3) & 1) * 8;
    const int aColB = (lane >> 4) * 16;
    const int bRow = (lane & 7) + (lane >> 4) * 8;
    const int bColB = ((lane >> 3) & 1) * 16;

    // hoisted swizzled relative offsets (kk toggles bit 5 post-swizzle)
    uint32_t aoffm[2], boffn[2];
#pragma unroll
    for (int mt = 0; mt < 2; mt++)
        aoffm[mt] = SW64((wm + mt * 16 + aRow) * 64 + aColB);
#pragma unroll
    for (int nb = 0; nb < 2; nb++)
        boffn[nb] = SW64((wn + nb * 16 + bRow) * 64 + bColB);

    int acc1[2][4][4];   // h*h
    int acc2[2][4][4];   // h*l + l*h
#pragma unroll
    for (int i = 0; i < 2; i++)
#pragma unroll
        for (int j = 0; j < 4; j++)
#pragma unroll
            for (int k = 0; k < 4; k++) { acc1[i][j][k] = 0; acc2[i][j][k] = 0; }

    load_stage(sb, 0, row0, col0, tid);
    load_stage(sb, 1, row0, col0, tid);
    load_stage(sb, 2, row0, col0, tid);

    for (int q = 0; q < KQ; q++) {
        if (q < KQ - 2)       asm volatile("cp.async.wait_group 2;\n" ::: "memory");
        else if (q == KQ - 2) asm volatile("cp.async.wait_group 1;\n" ::: "memory");
        else                  asm volatile("cp.async.wait_group 0;\n" ::: "memory");
        __syncthreads();

        if (q + 3 < KQ) load_stage(sb, q + 3, row0, col0, tid);

        uint32_t st = sb + (q & 3) * STAGE_BYTES;
#pragma unroll
        for (int kk = 0; kk < 2; kk++) {     // 2 x k32 per BK=64
            const uint32_t kx = kk * 32;
            uint32_t ah[2][4], al[2][4], wh[2][4], wl[2][4];
#pragma unroll
            for (int mt = 0; mt < 2; mt++) {
                uint32_t ra = st + (aoffm[mt] ^ kx);
                ldmx4(ah[mt], ra);
                ldmx4(al[mt], ra + OFF_AL);
            }
#pragma unroll
            for (int nb = 0; nb < 2; nb++) {
                uint32_t rb = st + (boffn[nb] ^ kx);
                ldmx4(wh[nb], rb + OFF_WH);
                ldmx4(wl[nb], rb + OFF_WL);
            }
#pragma unroll
            for (int mt = 0; mt < 2; mt++)
#pragma unroll
                for (int nt = 0; nt < 4; nt++) {
                    const uint32_t* bh = &wh[nt >> 1][(nt & 1) * 2];
                    const uint32_t* bl = &wl[nt >> 1][(nt & 1) * 2];
                    imma16832(acc1[mt][nt], ah[mt], bh);
                    imma16832(acc2[mt][nt], al[mt], bh);
                    imma16832(acc2[mt][nt], ah[mt], bl);
                }
        }
        // NOTE: no trailing __syncthreads needed — next iteration's top sync
        // (after wait_group) orders stage reuse: stage (q+3)&3 is only written
        // after every thread has finished reading it in iteration q-1.
    }

    // epilogue: out = valid ? sa*sw*(P1 + P23/256) + bias : 0
#pragma unroll
    for (int mt = 0; mt < 2; mt++) {
        int rb = row0 + wm + mt * 16 + (lane >> 2);
#pragma unroll
        for (int h2 = 0; h2 < 2; h2++) {
            int row = rb + h2 * 8;
            bool valid = row < nv;
            float sa = g_sa[row];
            float* orow = out + (size_t)row * D_DIM;
#pragma unroll
            for (int nt = 0; nt < 4; nt++) {
                int col = col0 + wn + nt * 8 + (lane & 3) * 2;
                float p0 = (float)acc1[mt][nt][h2 * 2 + 0]
                         + (float)acc2[mt][nt][h2 * 2 + 0] * 0.00390625f;
                float p1 = (float)acc1[mt][nt][h2 * 2 + 1]
                         + (float)acc2[mt][nt][h2 * 2 + 1] * 0.00390625f;
                float2 o;
                o.x = valid ? (p0 * sa * g_sw[col + 0] + bias[col + 0]) : 0.f;
                o.y = valid ? (p1 * sa * g_sw[col + 1] + bias[col + 1]) : 0.f;
                *(float2*)(orow + col) = o;
            }
        }
    }
}

// ============================================================
extern "C" void kernel_launch(void* const* d_in, const int* in_sizes, int n_in,
                              void* d_out, int out_size) {
    const float* hidden = (const float*)d_in[0];  // [1, T, H]
    const float* logits = (const float*)d_in[1];  // [1, T, V]
    const float* W      = (const float*)d_in[2];  // [D, H]
    const float* b      = (const float*)d_in[3];  // [D]
    float* out = (float*)d_out;                   // [1, T, D]

    cudaFuncSetAttribute(k_gemm_imma, cudaFuncAttributeMaxDynamicSharedMemorySize, SMEM_REQ);

    k_argmax<<<T_TOK / 256, 256>>>(logits);
    k_scan<<<1, 1024>>>();
    k_means<<<T_TOK, 256>>>(hidden);
    k_wquant<<<D_DIM, 256>>>(W);
    dim3 grid(D_DIM / BN, T_TOK / BM);
    k_gemm_imma<<<grid, 512, SMEM_REQ>>>(b, out);
}